// round 7
// baseline (speedup 1.0000x reference)
#include <cuda_runtime.h>
#include <cuda_bf16.h>
#include <cstdint>

#define Bb   8
#define Nn   4096
#define Mm   2048
#define DIN  256
#define DOUT 128

__device__ __nv_bfloat16 g_Qh [Bb*Mm*DOUT];
__device__ __nv_bfloat16 g_Ql [Bb*Mm*DOUT];
__device__ __nv_bfloat16 g_Kh [Bb*Mm*DOUT];
__device__ __nv_bfloat16 g_Kl [Bb*Mm*DOUT];
__device__ float         g_V  [Bb*Mm*DOUT];
__device__ __nv_bfloat16 g_Vth[Bb*DOUT*Mm];    // [b][e][m]
__device__ __nv_bfloat16 g_Vtl[Bb*DOUT*Mm];
__device__ __nv_bfloat16 g_Wth[3*DOUT*DIN];    // [wsel][n][k]
__device__ __nv_bfloat16 g_Wtl[3*DOUT*DIN];
__device__ __nv_bfloat16 g_Ah [(size_t)Bb*Mm*Mm];
__device__ __nv_bfloat16 g_Al [(size_t)Bb*Mm*Mm];

// ---------------- helpers ----------------
__device__ __forceinline__ uint32_t cvta_smem(const void* p) {
    uint32_t a;
    asm("{ .reg .u64 t; cvta.to.shared.u64 t, %1; cvt.u32.u64 %0, t; }" : "=r"(a) : "l"(p));
    return a;
}
__device__ __forceinline__ uint32_t b2pack(float a, float b) {
    uint16_t la = __bfloat16_as_ushort(__float2bfloat16(a));
    uint16_t lb = __bfloat16_as_ushort(__float2bfloat16(b));
    return (uint32_t)la | ((uint32_t)lb << 16);
}
__device__ __forceinline__ float bhi(float x) {
    return __bfloat162float(__float2bfloat16(x));
}
__device__ __forceinline__ void ldmA(uint32_t a[4], uint32_t addr) {
    asm volatile("ldmatrix.sync.aligned.m8n8.x4.shared.b16 {%0,%1,%2,%3}, [%4];"
        : "=r"(a[0]),"=r"(a[1]),"=r"(a[2]),"=r"(a[3]) : "r"(addr));
}
__device__ __forceinline__ void ldmB(uint32_t b[2], uint32_t addr) {
    asm volatile("ldmatrix.sync.aligned.m8n8.x2.shared.b16 {%0,%1}, [%2];"
        : "=r"(b[0]),"=r"(b[1]) : "r"(addr));
}
__device__ __forceinline__ void mma16816(float c[4], const uint32_t a[4], const uint32_t b[2]) {
    asm volatile("mma.sync.aligned.m16n8k16.row.col.f32.bf16.bf16.f32 "
        "{%0,%1,%2,%3}, {%4,%5,%6,%7}, {%8,%9}, {%0,%1,%2,%3};"
        : "+f"(c[0]),"+f"(c[1]),"+f"(c[2]),"+f"(c[3])
        : "r"(a[0]),"r"(a[1]),"r"(a[2]),"r"(a[3]), "r"(b[0]),"r"(b[1]));
}
#define CPA(d, s) asm volatile("cp.async.cg.shared.global [%0], [%1], 16;" :: "r"(d), "l"(s))
#define CPC()     asm volatile("cp.async.commit_group;" ::: "memory")
#define CPW1()    asm volatile("cp.async.wait_group 1;" ::: "memory")
#define CPW0()    asm volatile("cp.async.wait_group 0;" ::: "memory")

#define PIT 136
#define PITB 272
#define P64B 144

// ---------------------------------------------------------------------------
__global__ void prep_kernel(const float* __restrict__ Wq,
                            const float* __restrict__ Wk,
                            const float* __restrict__ Wv)
{
    const float* W = (blockIdx.x == 0) ? Wq : (blockIdx.x == 1) ? Wk : Wv;
    __nv_bfloat16* dh = g_Wth + blockIdx.x * DOUT * DIN;
    __nv_bfloat16* dl = g_Wtl + blockIdx.x * DOUT * DIN;
    for (int i = threadIdx.x; i < DOUT * (DIN/2); i += 256) {
        int n = i >> 7, k = (i & 127) * 2;
        float x0 = W[(size_t)k*DOUT + n];
        float x1 = W[(size_t)(k+1)*DOUT + n];
        *reinterpret_cast<uint32_t*>(dh + (size_t)n*DIN + k) = b2pack(x0, x1);
        *reinterpret_cast<uint32_t*>(dl + (size_t)n*DIN + k) =
            b2pack(x0 - bhi(x0), x1 - bhi(x1));
    }
}

// ---------------------------------------------------------------------------
// projmma: 512 threads, 16 warps (8m x 2n), warp tile 16x64.
// ---------------------------------------------------------------------------
__global__ __launch_bounds__(512, 1)
void projmma_kernel(const float* __restrict__ Y, const int* __restrict__ idx,
                    const float* __restrict__ bq, const float* __restrict__ bk,
                    const float* __restrict__ bv)
{
    extern __shared__ char smraw[];
    char* Ah = smraw;
    char* Al = smraw + 69632;
    char* Bh = smraw + 139264;
    char* Bl = smraw + 174080;
    float* Vs = reinterpret_cast<float*>(Bh);
    __shared__ int idxs[128];

    const int tid = threadIdx.x, lane = tid & 31, wid = tid >> 5;
    const int wm = wid >> 1, wn = wid & 1;
    const int row0 = blockIdx.x * 128;
    const int b    = row0 / Mm;
    const int m0   = row0 % Mm;

    if (tid < 128) idxs[tid] = idx[b*Mm + m0 + tid];
    __syncthreads();

    for (int i = tid; i < 128*64; i += 512) {
        int row = i >> 6, c4 = i & 63;
        float4 y = *reinterpret_cast<const float4*>(
            Y + ((size_t)b*Nn + idxs[row])*DIN + c4*4);
        int kc = c4 >> 5;
        uint32_t off = (uint32_t)(kc*34816 + row*PITB + (c4 & 31)*8);
        *reinterpret_cast<uint2*>(Ah + off) =
            make_uint2(b2pack(y.x, y.y), b2pack(y.z, y.w));
        *reinterpret_cast<uint2*>(Al + off) =
            make_uint2(b2pack(y.x-bhi(y.x), y.y-bhi(y.y)),
                       b2pack(y.z-bhi(y.z), y.w-bhi(y.w)));
    }

    const uint32_t sAh = cvta_smem(Ah), sAl = cvta_smem(Al);
    const uint32_t sBh = cvta_smem(Bh), sBl = cvta_smem(Bl);

    const int aRow = wm*16 + (lane & 15);
    const int aKb  = (lane >> 4) * 8;
    const int bRow = wn*64 + (lane & 7);
    const int bKb  = ((lane >> 3) & 1) * 8;

    #pragma unroll 1
    for (int wsel = 0; wsel < 3; wsel++) {
        float acc[8][4] = {};
        #pragma unroll 1
        for (int kc = 0; kc < 2; kc++) {
            __syncthreads();
            const __nv_bfloat16* wh = g_Wth + (size_t)wsel*DOUT*DIN + kc*128;
            const __nv_bfloat16* wl = g_Wtl + (size_t)wsel*DOUT*DIN + kc*128;
            for (int i = tid; i < 128*16; i += 512) {
                int n = i >> 4, c8 = i & 15;
                uint32_t off = (uint32_t)(n*PITB + c8*16);
                size_t go = (size_t)n*DIN + c8*8;
                *reinterpret_cast<uint4*>(Bh + off) =
                    *reinterpret_cast<const uint4*>(wh + go);
                *reinterpret_cast<uint4*>(Bl + off) =
                    *reinterpret_cast<const uint4*>(wl + go);
            }
            __syncthreads();
            uint32_t aBase = kc * 34816;
            #pragma unroll
            for (int term = 0; term < 3; term++) {
                uint32_t sA = ((term == 2) ? sAl : sAh) + aBase;
                uint32_t sB = (term == 1) ? sBl : sBh;
                #pragma unroll
                for (int ks = 0; ks < 8; ks++) {
                    uint32_t af[4], bf[8][2];
                    ldmA(af, sA + (aRow*PIT + aKb + ks*16)*2);
                    #pragma unroll
                    for (int j = 0; j < 8; j++)
                        ldmB(bf[j], sB + ((bRow + j*8)*PIT + bKb + ks*16)*2);
                    #pragma unroll
                    for (int j = 0; j < 8; j++)
                        mma16816(acc[j], af, bf[j]);
                }
            }
        }

        const float* bp = (wsel == 0) ? bq : (wsel == 1) ? bk : bv;
        float bias2[8][2];
        #pragma unroll
        for (int j = 0; j < 8; j++) {
            int c = wn*64 + j*8 + (lane & 3)*2;
            bias2[j][0] = bp[c]; bias2[j][1] = bp[c+1];
        }

        if (wsel < 2) {
            const float s = (wsel == 0) ? 0.0625f : 1.0f;
            __nv_bfloat16* gh = (wsel == 0) ? g_Qh : g_Kh;
            __nv_bfloat16* gl = (wsel == 0) ? g_Ql : g_Kl;
            #pragma unroll
            for (int j = 0; j < 8; j++) {
                int r = wm*16 + (lane >> 2);
                int c = wn*64 + j*8 + (lane & 3)*2;
                float q0 = (acc[j][0] + bias2[j][0]) * s;
                float q1 = (acc[j][1] + bias2[j][1]) * s;
                float q2 = (acc[j][2] + bias2[j][0]) * s;
                float q3 = (acc[j][3] + bias2[j][1]) * s;
                size_t o0 = ((size_t)(b*Mm + m0 + r))*DOUT + c;
                size_t o1 = ((size_t)(b*Mm + m0 + r + 8))*DOUT + c;
                *reinterpret_cast<uint32_t*>(gh + o0) = b2pack(q0, q1);
                *reinterpret_cast<uint32_t*>(gl + o0) =
                    b2pack(q0 - bhi(q0), q1 - bhi(q1));
                *reinterpret_cast<uint32_t*>(gh + o1) = b2pack(q2, q3);
                *reinterpret_cast<uint32_t*>(gl + o1) =
                    b2pack(q2 - bhi(q2), q3 - bhi(q3));
            }
        } else {
            __syncthreads();
            #pragma unroll
            for (int j = 0; j < 8; j++) {
                int r = wm*16 + (lane >> 2);
                int c = wn*64 + j*8 + (lane & 3)*2;
                float v0 = fmaxf(acc[j][0] + bias2[j][0], 0.f);
                float v1 = fmaxf(acc[j][1] + bias2[j][1], 0.f);
                float v2 = fmaxf(acc[j][2] + bias2[j][0], 0.f);
                float v3 = fmaxf(acc[j][3] + bias2[j][1], 0.f);
                *reinterpret_cast<float2*>(
                    g_V + ((size_t)(b*Mm + m0 + r))*DOUT + c) = make_float2(v0, v1);
                *reinterpret_cast<float2*>(
                    g_V + ((size_t)(b*Mm + m0 + r + 8))*DOUT + c) = make_float2(v2, v3);
                Vs[r*132 + c]       = v0;
                Vs[r*132 + c + 1]   = v1;
                Vs[(r+8)*132 + c]   = v2;
                Vs[(r+8)*132 + c+1] = v3;
            }
            __syncthreads();
            int e = tid & 127, quarter = tid >> 7;   // 4 quarters x 32 m
            int mb = quarter * 32;
            uint32_t hp[16], lp[16];
            #pragma unroll
            for (int t = 0; t < 16; t++) {
                float x0 = Vs[(mb + 2*t    )*132 + e];
                float x1 = Vs[(mb + 2*t + 1)*132 + e];
                hp[t] = b2pack(x0, x1);
                lp[t] = b2pack(x0 - bhi(x0), x1 - bhi(x1));
            }
            uint4* dh = reinterpret_cast<uint4*>(
                g_Vth + ((size_t)b*DOUT + e)*Mm + m0 + mb);
            uint4* dl = reinterpret_cast<uint4*>(
                g_Vtl + ((size_t)b*DOUT + e)*Mm + m0 + mb);
            #pragma unroll
            for (int q = 0; q < 4; q++) {
                dh[q] = make_uint4(hp[4*q],hp[4*q+1],hp[4*q+2],hp[4*q+3]);
                dl[q] = make_uint4(lp[4*q],lp[4*q+1],lp[4*q+2],lp[4*q+3]);
            }
        }
    }
}

// ---------------------------------------------------------------------------
// attnA: 512 threads, 16 warps (8m x 2n), warp tile 16x32 over 64-key chunks.
// ---------------------------------------------------------------------------
__global__ __launch_bounds__(512, 1)
void attnA_kernel(float* __restrict__ att)
{
    extern __shared__ char smraw[];
    const int tid = threadIdx.x, lane = tid & 31, wid = tid >> 5;
    const int b = blockIdx.y, m0 = blockIdx.x * 128;
    const int wm = wid >> 1, wn = wid & 1;

    char* Qh = smraw;
    char* Ql = smraw + 34816;
    char* Kb = smraw + 69632;
    const uint32_t sQh = cvta_smem(Qh), sQl = cvta_smem(Ql);
    const uint32_t sKb = cvta_smem(Kb);

    auto issueK = [&](int ch, int buf) {
        const uint32_t dbase = sKb + buf*34816;
        #pragma unroll
        for (int t = 0; t < 4; t++) {
            int i = tid + t*512;
            int tile = i >> 10, row = (i >> 4) & 63, p = i & 15;
            const __nv_bfloat16* src = (tile ? g_Kl : g_Kh)
                + ((size_t)(b*Mm + ch*64 + row))*DOUT + p*8;
            CPA(dbase + tile*17408 + row*PITB + p*16, src);
        }
        CPC();
    };

    issueK(0, 0);

    {
        const uint4* qh = reinterpret_cast<const uint4*>(g_Qh + ((size_t)b*Mm + m0)*DOUT);
        const uint4* ql = reinterpret_cast<const uint4*>(g_Ql + ((size_t)b*Mm + m0)*DOUT);
        for (int i = tid; i < 128*16; i += 512) {
            int row = i >> 4, c8 = i & 15;
            *reinterpret_cast<uint4*>(Qh + row*PITB + c8*16) = qh[i];
            *reinterpret_cast<uint4*>(Ql + row*PITB + c8*16) = ql[i];
        }
    }

    const int aRow = wm*16 + (lane & 15);
    const int aKb  = (lane >> 4) * 8;
    const int bRow = wn*32 + (lane & 7);
    const int bKb  = ((lane >> 3) & 1) * 8;

    #pragma unroll 1
    for (int ch = 0; ch < 32; ch++) {
        if (ch < 31) issueK(ch + 1, (ch + 1) & 1);
        if (ch < 31) { CPW1(); } else { CPW0(); }
        __syncthreads();

        const uint32_t kh = sKb + (ch & 1)*34816;
        const uint32_t kl = kh + 17408;

        float acc[4][4] = {};
        #pragma unroll
        for (int term = 0; term < 3; term++) {
            uint32_t sA = (term == 2) ? sQl : sQh;
            uint32_t sB = (term == 1) ? kl : kh;
            #pragma unroll
            for (int ks = 0; ks < 8; ks++) {
                uint32_t af[4], bf[4][2];
                ldmA(af, sA + (aRow*PIT + aKb + ks*16)*2);
                #pragma unroll
                for (int j = 0; j < 4; j++)
                    ldmB(bf[j], sB + (bRow + j*8)*PITB + (bKb + ks*16)*2);
                #pragma unroll
                for (int j = 0; j < 4; j++)
                    mma16816(acc[j], af, bf[j]);
            }
        }
        __syncthreads();

        #pragma unroll
        for (int j = 0; j < 4; j++) {
            int r = wm*16 + (lane >> 2);
            int c = ch*64 + wn*32 + j*8 + (lane & 3)*2;
            *reinterpret_cast<float2*>(
                att + ((size_t)(b*Mm + m0 + r))*Mm + c) =
                make_float2(acc[j][0], acc[j][1]);
            *reinterpret_cast<float2*>(
                att + ((size_t)(b*Mm + m0 + r + 8))*Mm + c) =
                make_float2(acc[j][2], acc[j][3]);
        }
    }
    __syncthreads();

    // softmax: warp wid owns rows [wid*8, wid*8+8)
    #pragma unroll 1
    for (int rr = 0; rr < 8; rr++) {
        size_t rowi = (size_t)(b*Mm + m0 + wid*8 + rr);
        float* row = att + rowi*Mm;
        float4 v[16];
        #pragma unroll
        for (int j = 0; j < 16; j++) v[j] = reinterpret_cast<float4*>(row)[lane + j*32];
        float mx = -1e30f;
        #pragma unroll
        for (int j = 0; j < 16; j++)
            mx = fmaxf(mx, fmaxf(fmaxf(v[j].x, v[j].y), fmaxf(v[j].z, v[j].w)));
        #pragma unroll
        for (int o = 16; o > 0; o >>= 1) mx = fmaxf(mx, __shfl_xor_sync(0xffffffffu, mx, o));
        float sum = 0.f;
        #pragma unroll
        for (int j = 0; j < 16; j++) {
            v[j].x = __expf(v[j].x - mx); v[j].y = __expf(v[j].y - mx);
            v[j].z = __expf(v[j].z - mx); v[j].w = __expf(v[j].w - mx);
            sum += (v[j].x + v[j].y) + (v[j].z + v[j].w);
        }
        #pragma unroll
        for (int o = 16; o > 0; o >>= 1) sum += __shfl_xor_sync(0xffffffffu, sum, o);
        float inv = 1.f / sum;
        uint2* ah = reinterpret_cast<uint2*>(g_Ah + rowi*Mm);
        uint2* al = reinterpret_cast<uint2*>(g_Al + rowi*Mm);
        #pragma unroll
        for (int j = 0; j < 16; j++) {
            v[j].x *= inv; v[j].y *= inv; v[j].z *= inv; v[j].w *= inv;
            reinterpret_cast<float4*>(row)[lane + j*32] = v[j];
            ah[lane + j*32] = make_uint2(b2pack(v[j].x, v[j].y), b2pack(v[j].z, v[j].w));
            al[lane + j*32] = make_uint2(
                b2pack(v[j].x - bhi(v[j].x), v[j].y - bhi(v[j].y)),
                b2pack(v[j].z - bhi(v[j].z), v[j].w - bhi(v[j].w)));
        }
    }
}

// ---------------------------------------------------------------------------
// attnC: 512 threads, 16 warps (8m x 2n), warp tile 16x64.
// ---------------------------------------------------------------------------
__global__ __launch_bounds__(512, 1)
void attnC_kernel(float* __restrict__ out)
{
    extern __shared__ char smraw[];
    const int tid = threadIdx.x, lane = tid & 31, wid = tid >> 5;
    const int b = blockIdx.y, m0 = blockIdx.x * 128;
    const int wm = wid >> 1, wn = wid & 1;

    const uint32_t sb = cvta_smem(smraw);

    auto issueC = [&](int ch, int buf) {
        const uint32_t dbase = sb + buf*73728;
        #pragma unroll
        for (int t = 0; t < 8; t++) {
            int i = tid + t*512;
            int tile = i >> 10, row = (i >> 3) & 127, p = i & 7;
            const __nv_bfloat16* src;
            if (tile == 0)
                src = g_Ah + ((size_t)(b*Mm + m0 + row))*Mm + ch*64 + p*8;
            else if (tile == 1)
                src = g_Al + ((size_t)(b*Mm + m0 + row))*Mm + ch*64 + p*8;
            else if (tile == 2)
                src = g_Vth + ((size_t)(b*DOUT + row))*Mm + ch*64 + p*8;
            else
                src = g_Vtl + ((size_t)(b*DOUT + row))*Mm + ch*64 + p*8;
            CPA(dbase + tile*18432 + row*P64B + p*16, src);
        }
        CPC();
    };

    issueC(0, 0);

    const int aRow = wm*16 + (lane & 15);
    const int aKb  = (lane >> 4) * 8;
    const int bRow = wn*64 + (lane & 7);
    const int bKb  = ((lane >> 3) & 1) * 8;

    float acc[8][4] = {};

    #pragma unroll 1
    for (int ch = 0; ch < 32; ch++) {
        if (ch < 31) issueC(ch + 1, (ch + 1) & 1);
        if (ch < 31) { CPW1(); } else { CPW0(); }
        __syncthreads();

        const uint32_t base = sb + (ch & 1)*73728;
        const uint32_t tAh = base, tAl = base + 18432;
        const uint32_t tBh = base + 36864, tBl = base + 55296;

        #pragma unroll
        for (int term = 0; term < 3; term++) {
            uint32_t sA = (term == 2) ? tAl : tAh;
            uint32_t sB = (term == 1) ? tBl : tBh;
            #pragma unroll
            for (int ks = 0; ks < 4; ks++) {
                uint32_t af[4], bf[8][2];
                ldmA(af, sA + aRow*P64B + (aKb + ks*16)*2);
                #pragma unroll
                for (int j = 0; j < 8; j++)
                    ldmB(bf[j], sB + (bRow + j*8)*P64B + (bKb + ks*16)*2);
                #pragma unroll
                for (int j = 0; j < 8; j++)
                    mma16816(acc[j], af, bf[j]);
            }
        }
        __syncthreads();
    }

    float* Ss = reinterpret_cast<float*>(smraw);
    #pragma unroll
    for (int j = 0; j < 8; j++) {
        int r = wm*16 + (lane >> 2);
        int c = wn*64 + j*8 + (lane & 3)*2;
        Ss[r*132 + c]         = acc[j][0];
        Ss[r*132 + c + 1]     = acc[j][1];
        Ss[(r+8)*132 + c]     = acc[j][2];
        Ss[(r+8)*132 + c + 1] = acc[j][3];
    }
    __syncthreads();

    #pragma unroll 1
    for (int rr = 0; rr < 8; rr++) {
        int r = wid*8 + rr;
        float a0 = Ss[r*132 + lane],      a1 = Ss[r*132 + lane + 32];
        float a2 = Ss[r*132 + lane + 64], a3 = Ss[r*132 + lane + 96];
        float ss = a0*a0 + a1*a1 + a2*a2 + a3*a3;
        #pragma unroll
        for (int o = 16; o > 0; o >>= 1) ss += __shfl_xor_sync(0xffffffffu, ss, o);
        float inv1 = rsqrtf(fmaxf(ss, 1e-12f));
        const float* vrow = g_V + ((size_t)b*Mm + m0 + r)*DOUT;
        float t0 = vrow[lane]      + a0*inv1;
        float t1 = vrow[lane + 32] + a1*inv1;
        float t2 = vrow[lane + 64] + a2*inv1;
        float t3 = vrow[lane + 96] + a3*inv1;
        float ss2 = t0*t0 + t1*t1 + t2*t2 + t3*t3;
        #pragma unroll
        for (int o = 16; o > 0; o >>= 1) ss2 += __shfl_xor_sync(0xffffffffu, ss2, o);
        float inv2 = rsqrtf(fmaxf(ss2, 1e-12f));
        float* orow = out + ((size_t)b*Mm + m0 + r)*DOUT;
        orow[lane]      = t0*inv2;
        orow[lane + 32] = t1*inv2;
        orow[lane + 64] = t2*inv2;
        orow[lane + 96] = t3*inv2;
    }
}

// ---------------------------------------------------------------------------
extern "C" void kernel_launch(void* const* d_in, const int* in_sizes, int n_in,
                              void* d_out, int out_size)
{
    const float* Y   = (const float*)d_in[0];
    const int*   idx = (const int*)  d_in[1];
    const float* Wq  = (const float*)d_in[2];
    const float* bq  = (const float*)d_in[3];
    const float* Wk  = (const float*)d_in[4];
    const float* bk  = (const float*)d_in[5];
    const float* Wv  = (const float*)d_in[6];
    const float* bv  = (const float*)d_in[7];

    float* out = (float*)d_out;                       // [8,2048,128]
    float* att = out + (size_t)Bb*Mm*DOUT;            // [8,2048,2048]

    const int smemP = 208896;
    const int smemA = 139264;
    const int smemC = 147456;

    cudaFuncSetAttribute(projmma_kernel, cudaFuncAttributeMaxDynamicSharedMemorySize, smemP);
    cudaFuncSetAttribute(attnA_kernel,   cudaFuncAttributeMaxDynamicSharedMemorySize, smemA);
    cudaFuncSetAttribute(attnC_kernel,   cudaFuncAttributeMaxDynamicSharedMemorySize, smemC);

    prep_kernel<<<3, 256>>>(Wq, Wk, Wv);
    projmma_kernel<<<(Bb*Mm)/128, 512, smemP>>>(Y, idx, bq, bk, bv);
    attnA_kernel<<<dim3(Mm/128, Bb), 512, smemA>>>(att);
    attnC_kernel<<<dim3(Mm/128, Bb), 512, smemC>>>(out);
}

// round 8
// speedup vs baseline: 1.0121x; 1.0121x over previous
#include <cuda_runtime.h>
#include <cuda_bf16.h>
#include <cstdint>

#define Bb   8
#define Nn   4096
#define Mm   2048
#define DIN  256
#define DOUT 128

__device__ __nv_bfloat16 g_Qh [Bb*Mm*DOUT];
__device__ __nv_bfloat16 g_Ql [Bb*Mm*DOUT];
__device__ __nv_bfloat16 g_Kh [Bb*Mm*DOUT];
__device__ __nv_bfloat16 g_Kl [Bb*Mm*DOUT];
__device__ float         g_V  [Bb*Mm*DOUT];
__device__ __nv_bfloat16 g_Vth[Bb*DOUT*Mm];    // [b][e][m]
__device__ __nv_bfloat16 g_Vtl[Bb*DOUT*Mm];
__device__ __nv_bfloat16 g_Wth[3*DOUT*DIN];    // [wsel][n][k]
__device__ __nv_bfloat16 g_Wtl[3*DOUT*DIN];
__device__ __nv_bfloat16 g_Ah [(size_t)Bb*Mm*Mm];
__device__ __nv_bfloat16 g_Al [(size_t)Bb*Mm*Mm];

// ---------------- helpers ----------------
__device__ __forceinline__ uint32_t cvta_smem(const void* p) {
    uint32_t a;
    asm("{ .reg .u64 t; cvta.to.shared.u64 t, %1; cvt.u32.u64 %0, t; }" : "=r"(a) : "l"(p));
    return a;
}
__device__ __forceinline__ uint32_t b2pack(float a, float b) {
    uint16_t la = __bfloat16_as_ushort(__float2bfloat16(a));
    uint16_t lb = __bfloat16_as_ushort(__float2bfloat16(b));
    return (uint32_t)la | ((uint32_t)lb << 16);
}
__device__ __forceinline__ float bhi(float x) {
    return __bfloat162float(__float2bfloat16(x));
}
__device__ __forceinline__ void ldmA(uint32_t a[4], uint32_t addr) {
    asm volatile("ldmatrix.sync.aligned.m8n8.x4.shared.b16 {%0,%1,%2,%3}, [%4];"
        : "=r"(a[0]),"=r"(a[1]),"=r"(a[2]),"=r"(a[3]) : "r"(addr));
}
// x4 B-load: returns fragments for two adjacent j (lanes 16-31 address the j+1 rows)
__device__ __forceinline__ void ldmB4(uint32_t b[4], uint32_t addr) {
    asm volatile("ldmatrix.sync.aligned.m8n8.x4.shared.b16 {%0,%1,%2,%3}, [%4];"
        : "=r"(b[0]),"=r"(b[1]),"=r"(b[2]),"=r"(b[3]) : "r"(addr));
}
__device__ __forceinline__ void mma16816(float c[4], const uint32_t a[4], const uint32_t b[2]) {
    asm volatile("mma.sync.aligned.m16n8k16.row.col.f32.bf16.bf16.f32 "
        "{%0,%1,%2,%3}, {%4,%5,%6,%7}, {%8,%9}, {%0,%1,%2,%3};"
        : "+f"(c[0]),"+f"(c[1]),"+f"(c[2]),"+f"(c[3])
        : "r"(a[0]),"r"(a[1]),"r"(a[2]),"r"(a[3]), "r"(b[0]),"r"(b[1]));
}
#define CPA(d, s) asm volatile("cp.async.cg.shared.global [%0], [%1], 16;" :: "r"(d), "l"(s))
#define CPC()     asm volatile("cp.async.commit_group;" ::: "memory")
#define CPW1()    asm volatile("cp.async.wait_group 1;" ::: "memory")
#define CPW0()    asm volatile("cp.async.wait_group 0;" ::: "memory")

#define PIT 136
#define PITB 272
#define P64B 144

// ---------------------------------------------------------------------------
__global__ void prep_kernel(const float* __restrict__ Wq,
                            const float* __restrict__ Wk,
                            const float* __restrict__ Wv)
{
    const float* W = (blockIdx.x == 0) ? Wq : (blockIdx.x == 1) ? Wk : Wv;
    __nv_bfloat16* dh = g_Wth + blockIdx.x * DOUT * DIN;
    __nv_bfloat16* dl = g_Wtl + blockIdx.x * DOUT * DIN;
    for (int i = threadIdx.x; i < DOUT * (DIN/2); i += 256) {
        int n = i >> 7, k = (i & 127) * 2;
        float x0 = W[(size_t)k*DOUT + n];
        float x1 = W[(size_t)(k+1)*DOUT + n];
        *reinterpret_cast<uint32_t*>(dh + (size_t)n*DIN + k) = b2pack(x0, x1);
        *reinterpret_cast<uint32_t*>(dl + (size_t)n*DIN + k) =
            b2pack(x0 - bhi(x0), x1 - bhi(x1));
    }
}

// ---------------------------------------------------------------------------
// projmma: 512 threads, 16 warps (8m x 2n), warp tile 16x64.
// ---------------------------------------------------------------------------
__global__ __launch_bounds__(512, 1)
void projmma_kernel(const float* __restrict__ Y, const int* __restrict__ idx,
                    const float* __restrict__ bq, const float* __restrict__ bk,
                    const float* __restrict__ bv)
{
    extern __shared__ char smraw[];
    char* Ah = smraw;
    char* Al = smraw + 69632;
    char* Bh = smraw + 139264;
    char* Bl = smraw + 174080;
    float* Vs = reinterpret_cast<float*>(Bh);
    __shared__ int idxs[128];

    const int tid = threadIdx.x, lane = tid & 31, wid = tid >> 5;
    const int wm = wid >> 1, wn = wid & 1;
    const int row0 = blockIdx.x * 128;
    const int b    = row0 / Mm;
    const int m0   = row0 % Mm;

    if (tid < 128) idxs[tid] = idx[b*Mm + m0 + tid];
    __syncthreads();

    for (int i = tid; i < 128*64; i += 512) {
        int row = i >> 6, c4 = i & 63;
        float4 y = *reinterpret_cast<const float4*>(
            Y + ((size_t)b*Nn + idxs[row])*DIN + c4*4);
        int kc = c4 >> 5;
        uint32_t off = (uint32_t)(kc*34816 + row*PITB + (c4 & 31)*8);
        *reinterpret_cast<uint2*>(Ah + off) =
            make_uint2(b2pack(y.x, y.y), b2pack(y.z, y.w));
        *reinterpret_cast<uint2*>(Al + off) =
            make_uint2(b2pack(y.x-bhi(y.x), y.y-bhi(y.y)),
                       b2pack(y.z-bhi(y.z), y.w-bhi(y.w)));
    }

    const uint32_t sAh = cvta_smem(Ah), sAl = cvta_smem(Al);
    const uint32_t sBh = cvta_smem(Bh), sBl = cvta_smem(Bl);

    const int aRow  = wm*16 + (lane & 15);
    const int aKb   = (lane >> 4) * 8;
    const int bRow4 = wn*64 + ((lane >> 4) << 3) + (lane & 7);
    const int bK4   = ((lane >> 3) & 1) * 8;

    #pragma unroll 1
    for (int wsel = 0; wsel < 3; wsel++) {
        float acc[8][4] = {};
        #pragma unroll 1
        for (int kc = 0; kc < 2; kc++) {
            __syncthreads();
            const __nv_bfloat16* wh = g_Wth + (size_t)wsel*DOUT*DIN + kc*128;
            const __nv_bfloat16* wl = g_Wtl + (size_t)wsel*DOUT*DIN + kc*128;
            for (int i = tid; i < 128*16; i += 512) {
                int n = i >> 4, c8 = i & 15;
                uint32_t off = (uint32_t)(n*PITB + c8*16);
                size_t go = (size_t)n*DIN + c8*8;
                *reinterpret_cast<uint4*>(Bh + off) =
                    *reinterpret_cast<const uint4*>(wh + go);
                *reinterpret_cast<uint4*>(Bl + off) =
                    *reinterpret_cast<const uint4*>(wl + go);
            }
            __syncthreads();
            uint32_t aBase = kc * 34816;
            #pragma unroll
            for (int term = 0; term < 3; term++) {
                uint32_t sA = ((term == 2) ? sAl : sAh) + aBase;
                uint32_t sB = (term == 1) ? sBl : sBh;
                #pragma unroll
                for (int ks = 0; ks < 8; ks++) {
                    uint32_t af[4];
                    ldmA(af, sA + (aRow*PIT + aKb + ks*16)*2);
                    #pragma unroll
                    for (int jj = 0; jj < 4; jj++) {
                        uint32_t bq4[4];
                        ldmB4(bq4, sB + ((bRow4 + jj*16)*PIT + bK4 + ks*16)*2);
                        mma16816(acc[2*jj],     af, bq4);
                        mma16816(acc[2*jj + 1], af, bq4 + 2);
                    }
                }
            }
        }

        const float* bp = (wsel == 0) ? bq : (wsel == 1) ? bk : bv;
        float bias2[8][2];
        #pragma unroll
        for (int j = 0; j < 8; j++) {
            int c = wn*64 + j*8 + (lane & 3)*2;
            bias2[j][0] = bp[c]; bias2[j][1] = bp[c+1];
        }

        if (wsel < 2) {
            const float s = (wsel == 0) ? 0.0625f : 1.0f;
            __nv_bfloat16* gh = (wsel == 0) ? g_Qh : g_Kh;
            __nv_bfloat16* gl = (wsel == 0) ? g_Ql : g_Kl;
            #pragma unroll
            for (int j = 0; j < 8; j++) {
                int r = wm*16 + (lane >> 2);
                int c = wn*64 + j*8 + (lane & 3)*2;
                float q0 = (acc[j][0] + bias2[j][0]) * s;
                float q1 = (acc[j][1] + bias2[j][1]) * s;
                float q2 = (acc[j][2] + bias2[j][0]) * s;
                float q3 = (acc[j][3] + bias2[j][1]) * s;
                size_t o0 = ((size_t)(b*Mm + m0 + r))*DOUT + c;
                size_t o1 = ((size_t)(b*Mm + m0 + r + 8))*DOUT + c;
                *reinterpret_cast<uint32_t*>(gh + o0) = b2pack(q0, q1);
                *reinterpret_cast<uint32_t*>(gl + o0) =
                    b2pack(q0 - bhi(q0), q1 - bhi(q1));
                *reinterpret_cast<uint32_t*>(gh + o1) = b2pack(q2, q3);
                *reinterpret_cast<uint32_t*>(gl + o1) =
                    b2pack(q2 - bhi(q2), q3 - bhi(q3));
            }
        } else {
            __syncthreads();
            #pragma unroll
            for (int j = 0; j < 8; j++) {
                int r = wm*16 + (lane >> 2);
                int c = wn*64 + j*8 + (lane & 3)*2;
                float v0 = fmaxf(acc[j][0] + bias2[j][0], 0.f);
                float v1 = fmaxf(acc[j][1] + bias2[j][1], 0.f);
                float v2 = fmaxf(acc[j][2] + bias2[j][0], 0.f);
                float v3 = fmaxf(acc[j][3] + bias2[j][1], 0.f);
                *reinterpret_cast<float2*>(
                    g_V + ((size_t)(b*Mm + m0 + r))*DOUT + c) = make_float2(v0, v1);
                *reinterpret_cast<float2*>(
                    g_V + ((size_t)(b*Mm + m0 + r + 8))*DOUT + c) = make_float2(v2, v3);
                Vs[r*132 + c]       = v0;
                Vs[r*132 + c + 1]   = v1;
                Vs[(r+8)*132 + c]   = v2;
                Vs[(r+8)*132 + c+1] = v3;
            }
            __syncthreads();
            int e = tid & 127, quarter = tid >> 7;
            int mb = quarter * 32;
            uint32_t hp[16], lp[16];
            #pragma unroll
            for (int t = 0; t < 16; t++) {
                float x0 = Vs[(mb + 2*t    )*132 + e];
                float x1 = Vs[(mb + 2*t + 1)*132 + e];
                hp[t] = b2pack(x0, x1);
                lp[t] = b2pack(x0 - bhi(x0), x1 - bhi(x1));
            }
            uint4* dh = reinterpret_cast<uint4*>(
                g_Vth + ((size_t)b*DOUT + e)*Mm + m0 + mb);
            uint4* dl = reinterpret_cast<uint4*>(
                g_Vtl + ((size_t)b*DOUT + e)*Mm + m0 + mb);
            #pragma unroll
            for (int q = 0; q < 4; q++) {
                dh[q] = make_uint4(hp[4*q],hp[4*q+1],hp[4*q+2],hp[4*q+3]);
                dl[q] = make_uint4(lp[4*q],lp[4*q+1],lp[4*q+2],lp[4*q+3]);
            }
        }
    }
}

// ---------------------------------------------------------------------------
// attnA: 512 threads, 3-stage cp.async ring, ONE barrier per chunk.
// smem: Qh 34816 | Ql 34816 | 3 x Kbuf 34816 = 174080.
// ---------------------------------------------------------------------------
__global__ __launch_bounds__(512, 1)
void attnA_kernel(float* __restrict__ att)
{
    extern __shared__ char smraw[];
    const int tid = threadIdx.x, lane = tid & 31, wid = tid >> 5;
    const int b = blockIdx.y, m0 = blockIdx.x * 128;
    const int wm = wid >> 1, wn = wid & 1;

    char* Qh = smraw;
    char* Ql = smraw + 34816;
    char* Kb = smraw + 69632;
    const uint32_t sQh = cvta_smem(Qh), sQl = cvta_smem(Ql);
    const uint32_t sKb = cvta_smem(Kb);

    auto issueK = [&](int ch, int st) {
        const uint32_t dbase = sKb + st*34816;
        #pragma unroll
        for (int t = 0; t < 4; t++) {
            int i = tid + t*512;
            int tile = i >> 10, row = (i >> 4) & 63, p = i & 15;
            const __nv_bfloat16* src = (tile ? g_Kl : g_Kh)
                + ((size_t)(b*Mm + ch*64 + row))*DOUT + p*8;
            CPA(dbase + tile*17408 + row*PITB + p*16, src);
        }
        CPC();
    };

    issueK(0, 0);

    {
        const uint4* qh = reinterpret_cast<const uint4*>(g_Qh + ((size_t)b*Mm + m0)*DOUT);
        const uint4* ql = reinterpret_cast<const uint4*>(g_Ql + ((size_t)b*Mm + m0)*DOUT);
        for (int i = tid; i < 128*16; i += 512) {
            int row = i >> 4, c8 = i & 15;
            *reinterpret_cast<uint4*>(Qh + row*PITB + c8*16) = qh[i];
            *reinterpret_cast<uint4*>(Ql + row*PITB + c8*16) = ql[i];
        }
    }

    const int aRow  = wm*16 + (lane & 15);
    const int aKb   = (lane >> 4) * 8;
    const int bRow4 = wn*32 + ((lane >> 4) << 3) + (lane & 7);
    const int bK4   = ((lane >> 3) & 1) * 8;

    int st = 0;
    #pragma unroll 1
    for (int ch = 0; ch < 32; ch++) {
        int nst = (st == 2) ? 0 : st + 1;
        if (ch < 31) issueK(ch + 1, nst);
        if (ch < 31) { CPW1(); } else { CPW0(); }
        __syncthreads();

        const uint32_t kh = sKb + st*34816;
        const uint32_t kl = kh + 17408;

        float acc[4][4] = {};
        #pragma unroll
        for (int term = 0; term < 3; term++) {
            uint32_t sA = (term == 2) ? sQl : sQh;
            uint32_t sB = (term == 1) ? kl : kh;
            #pragma unroll
            for (int ks = 0; ks < 8; ks++) {
                uint32_t af[4];
                ldmA(af, sA + (aRow*PIT + aKb + ks*16)*2);
                #pragma unroll
                for (int jj = 0; jj < 2; jj++) {
                    uint32_t bq4[4];
                    ldmB4(bq4, sB + (bRow4 + jj*16)*PITB + (bK4 + ks*16)*2);
                    mma16816(acc[2*jj],     af, bq4);
                    mma16816(acc[2*jj + 1], af, bq4 + 2);
                }
            }
        }

        #pragma unroll
        for (int j = 0; j < 4; j++) {
            int r = wm*16 + (lane >> 2);
            int c = ch*64 + wn*32 + j*8 + (lane & 3)*2;
            *reinterpret_cast<float2*>(
                att + ((size_t)(b*Mm + m0 + r))*Mm + c) =
                make_float2(acc[j][0], acc[j][1]);
            *reinterpret_cast<float2*>(
                att + ((size_t)(b*Mm + m0 + r + 8))*Mm + c) =
                make_float2(acc[j][2], acc[j][3]);
        }
        st = nst;
    }
    __syncthreads();

    // softmax: warp wid owns rows [wid*8, wid*8+8); emits fp32 + bf16 split
    #pragma unroll 1
    for (int rr = 0; rr < 8; rr++) {
        size_t rowi = (size_t)(b*Mm + m0 + wid*8 + rr);
        float* row = att + rowi*Mm;
        float4 v[16];
        #pragma unroll
        for (int j = 0; j < 16; j++) v[j] = reinterpret_cast<float4*>(row)[lane + j*32];
        float mx = -1e30f;
        #pragma unroll
        for (int j = 0; j < 16; j++)
            mx = fmaxf(mx, fmaxf(fmaxf(v[j].x, v[j].y), fmaxf(v[j].z, v[j].w)));
        #pragma unroll
        for (int o = 16; o > 0; o >>= 1) mx = fmaxf(mx, __shfl_xor_sync(0xffffffffu, mx, o));
        float sum = 0.f;
        #pragma unroll
        for (int j = 0; j < 16; j++) {
            v[j].x = __expf(v[j].x - mx); v[j].y = __expf(v[j].y - mx);
            v[j].z = __expf(v[j].z - mx); v[j].w = __expf(v[j].w - mx);
            sum += (v[j].x + v[j].y) + (v[j].z + v[j].w);
        }
        #pragma unroll
        for (int o = 16; o > 0; o >>= 1) sum += __shfl_xor_sync(0xffffffffu, sum, o);
        float inv = 1.f / sum;
        uint2* ah = reinterpret_cast<uint2*>(g_Ah + rowi*Mm);
        uint2* al = reinterpret_cast<uint2*>(g_Al + rowi*Mm);
        #pragma unroll
        for (int j = 0; j < 16; j++) {
            v[j].x *= inv; v[j].y *= inv; v[j].z *= inv; v[j].w *= inv;
            reinterpret_cast<float4*>(row)[lane + j*32] = v[j];
            ah[lane + j*32] = make_uint2(b2pack(v[j].x, v[j].y), b2pack(v[j].z, v[j].w));
            al[lane + j*32] = make_uint2(
                b2pack(v[j].x - bhi(v[j].x), v[j].y - bhi(v[j].y)),
                b2pack(v[j].z - bhi(v[j].z), v[j].w - bhi(v[j].w)));
        }
    }
}

// ---------------------------------------------------------------------------
// attnC: 512 threads, 3-stage cp.async ring, ONE barrier per chunk.
// smem: 3 x (Ah|Al|Bh|Bl each 18432) = 221184.
// ---------------------------------------------------------------------------
__global__ __launch_bounds__(512, 1)
void attnC_kernel(float* __restrict__ out)
{
    extern __shared__ char smraw[];
    const int tid = threadIdx.x, lane = tid & 31, wid = tid >> 5;
    const int b = blockIdx.y, m0 = blockIdx.x * 128;
    const int wm = wid >> 1, wn = wid & 1;

    const uint32_t sb = cvta_smem(smraw);

    auto issueC = [&](int ch, int st) {
        const uint32_t dbase = sb + st*73728;
        #pragma unroll
        for (int t = 0; t < 8; t++) {
            int i = tid + t*512;
            int tile = i >> 10, row = (i >> 3) & 127, p = i & 7;
            const __nv_bfloat16* src;
            if (tile == 0)
                src = g_Ah + ((size_t)(b*Mm + m0 + row))*Mm + ch*64 + p*8;
            else if (tile == 1)
                src = g_Al + ((size_t)(b*Mm + m0 + row))*Mm + ch*64 + p*8;
            else if (tile == 2)
                src = g_Vth + ((size_t)(b*DOUT + row))*Mm + ch*64 + p*8;
            else
                src = g_Vtl + ((size_t)(b*DOUT + row))*Mm + ch*64 + p*8;
            CPA(dbase + tile*18432 + row*P64B + p*16, src);
        }
        CPC();
    };

    issueC(0, 0);

    const int aRow  = wm*16 + (lane & 15);
    const int aKb   = (lane >> 4) * 8;
    const int bRow4 = wn*64 + ((lane >> 4) << 3) + (lane & 7);
    const int bK4   = ((lane >> 3) & 1) * 8;

    float acc[8][4] = {};

    int st = 0;
    #pragma unroll 1
    for (int ch = 0; ch < 32; ch++) {
        int nst = (st == 2) ? 0 : st + 1;
        if (ch < 31) issueC(ch + 1, nst);
        if (ch < 31) { CPW1(); } else { CPW0(); }
        __syncthreads();

        const uint32_t base = sb + st*73728;
        const uint32_t tAh = base, tAl = base + 18432;
        const uint32_t tBh = base + 36864, tBl = base + 55296;

        #pragma unroll
        for (int term = 0; term < 3; term++) {
            uint32_t sA = (term == 2) ? tAl : tAh;
            uint32_t sB = (term == 1) ? tBl : tBh;
            #pragma unroll
            for (int ks = 0; ks < 4; ks++) {
                uint32_t af[4];
                ldmA(af, sA + aRow*P64B + (aKb + ks*16)*2);
                #pragma unroll
                for (int jj = 0; jj < 4; jj++) {
                    uint32_t bq4[4];
                    ldmB4(bq4, sB + (bRow4 + jj*16)*P64B + (bK4 + ks*16)*2);
                    mma16816(acc[2*jj],     af, bq4);
                    mma16816(acc[2*jj + 1], af, bq4 + 2);
                }
            }
        }
        st = nst;
    }
    __syncthreads();   // all MMA done before Ss overwrites stage 0

    float* Ss = reinterpret_cast<float*>(smraw);
    #pragma unroll
    for (int j = 0; j < 8; j++) {
        int r = wm*16 + (lane >> 2);
        int c = wn*64 + j*8 + (lane & 3)*2;
        Ss[r*132 + c]         = acc[j][0];
        Ss[r*132 + c + 1]     = acc[j][1];
        Ss[(r+8)*132 + c]     = acc[j][2];
        Ss[(r+8)*132 + c + 1] = acc[j][3];
    }
    __syncthreads();

    #pragma unroll 1
    for (int rr = 0; rr < 8; rr++) {
        int r = wid*8 + rr;
        float a0 = Ss[r*132 + lane],      a1 = Ss[r*132 + lane + 32];
        float a2 = Ss[r*132 + lane + 64], a3 = Ss[r*132 + lane + 96];
        float ss = a0*a0 + a1*a1 + a2*a2 + a3*a3;
        #pragma unroll
        for (int o = 16; o > 0; o >>= 1) ss += __shfl_xor_sync(0xffffffffu, ss, o);
        float inv1 = rsqrtf(fmaxf(ss, 1e-12f));
        const float* vrow = g_V + ((size_t)b*Mm + m0 + r)*DOUT;
        float t0 = vrow[lane]      + a0*inv1;
        float t1 = vrow[lane + 32] + a1*inv1;
        float t2 = vrow[lane + 64] + a2*inv1;
        float t3 = vrow[lane + 96] + a3*inv1;
        float ss2 = t0*t0 + t1*t1 + t2*t2 + t3*t3;
        #pragma unroll
        for (int o = 16; o > 0; o >>= 1) ss2 += __shfl_xor_sync(0xffffffffu, ss2, o);
        float inv2 = rsqrtf(fmaxf(ss2, 1e-12f));
        float* orow = out + ((size_t)b*Mm + m0 + r)*DOUT;
        orow[lane]      = t0*inv2;
        orow[lane + 32] = t1*inv2;
        orow[lane + 64] = t2*inv2;
        orow[lane + 96] = t3*inv2;
    }
}

// ---------------------------------------------------------------------------
extern "C" void kernel_launch(void* const* d_in, const int* in_sizes, int n_in,
                              void* d_out, int out_size)
{
    const float* Y   = (const float*)d_in[0];
    const int*   idx = (const int*)  d_in[1];
    const float* Wq  = (const float*)d_in[2];
    const float* bq  = (const float*)d_in[3];
    const float* Wk  = (const float*)d_in[4];
    const float* bk  = (const float*)d_in[5];
    const float* Wv  = (const float*)d_in[6];
    const float* bv  = (const float*)d_in[7];

    float* out = (float*)d_out;                       // [8,2048,128]
    float* att = out + (size_t)Bb*Mm*DOUT;            // [8,2048,2048]

    const int smemP = 208896;
    const int smemA = 174080;
    const int smemC = 221184;

    cudaFuncSetAttribute(projmma_kernel, cudaFuncAttributeMaxDynamicSharedMemorySize, smemP);
    cudaFuncSetAttribute(attnA_kernel,   cudaFuncAttributeMaxDynamicSharedMemorySize, smemA);
    cudaFuncSetAttribute(attnC_kernel,   cudaFuncAttributeMaxDynamicSharedMemorySize, smemC);

    prep_kernel<<<3, 256>>>(Wq, Wk, Wv);
    projmma_kernel<<<(Bb*Mm)/128, 512, smemP>>>(Y, idx, bq, bk, bv);
    attnA_kernel<<<dim3(Mm/128, Bb), 512, smemA>>>(att);
    attnC_kernel<<<dim3(Mm/128, Bb), 512, smemC>>>(out);
}

// round 9
// speedup vs baseline: 1.0461x; 1.0337x over previous
#include <cuda_runtime.h>
#include <cuda_bf16.h>
#include <cstdint>

#define Bb   8
#define Nn   4096
#define Mm   2048
#define DIN  256
#define DOUT 128

__device__ __nv_bfloat16 g_Qh [Bb*Mm*DOUT];
__device__ __nv_bfloat16 g_Ql [Bb*Mm*DOUT];
__device__ __nv_bfloat16 g_Kh [Bb*Mm*DOUT];
__device__ __nv_bfloat16 g_Kl [Bb*Mm*DOUT];
__device__ float         g_V  [Bb*Mm*DOUT];
__device__ __nv_bfloat16 g_Vth[Bb*DOUT*Mm];    // [b][e][m]
__device__ __nv_bfloat16 g_Vtl[Bb*DOUT*Mm];
__device__ __nv_bfloat16 g_Wth[3*DOUT*DIN];    // [wsel][n][k]
__device__ __nv_bfloat16 g_Wtl[3*DOUT*DIN];
__device__ __nv_bfloat16 g_Ah [(size_t)Bb*Mm*Mm];
__device__ __nv_bfloat16 g_Al [(size_t)Bb*Mm*Mm];

// ---------------- helpers ----------------
__device__ __forceinline__ uint32_t cvta_smem(const void* p) {
    uint32_t a;
    asm("{ .reg .u64 t; cvta.to.shared.u64 t, %1; cvt.u32.u64 %0, t; }" : "=r"(a) : "l"(p));
    return a;
}
__device__ __forceinline__ uint32_t b2pack(float a, float b) {
    uint16_t la = __bfloat16_as_ushort(__float2bfloat16(a));
    uint16_t lb = __bfloat16_as_ushort(__float2bfloat16(b));
    return (uint32_t)la | ((uint32_t)lb << 16);
}
__device__ __forceinline__ float bhi(float x) {
    return __bfloat162float(__float2bfloat16(x));
}
__device__ __forceinline__ void ldmA(uint32_t a[4], uint32_t addr) {
    asm volatile("ldmatrix.sync.aligned.m8n8.x4.shared.b16 {%0,%1,%2,%3}, [%4];"
        : "=r"(a[0]),"=r"(a[1]),"=r"(a[2]),"=r"(a[3]) : "r"(addr));
}
// x4 B-load: fragments for two adjacent j (lanes 16-31 address the j+1 rows)
__device__ __forceinline__ void ldmB4(uint32_t b[4], uint32_t addr) {
    asm volatile("ldmatrix.sync.aligned.m8n8.x4.shared.b16 {%0,%1,%2,%3}, [%4];"
        : "=r"(b[0]),"=r"(b[1]),"=r"(b[2]),"=r"(b[3]) : "r"(addr));
}
__device__ __forceinline__ void mma16816(float c[4], const uint32_t a[4], const uint32_t b[2]) {
    asm volatile("mma.sync.aligned.m16n8k16.row.col.f32.bf16.bf16.f32 "
        "{%0,%1,%2,%3}, {%4,%5,%6,%7}, {%8,%9}, {%0,%1,%2,%3};"
        : "+f"(c[0]),"+f"(c[1]),"+f"(c[2]),"+f"(c[3])
        : "r"(a[0]),"r"(a[1]),"r"(a[2]),"r"(a[3]), "r"(b[0]),"r"(b[1]));
}
#define CPA(d, s) asm volatile("cp.async.cg.shared.global [%0], [%1], 16;" :: "r"(d), "l"(s))
#define CPC()     asm volatile("cp.async.commit_group;" ::: "memory")
#define CPW1()    asm volatile("cp.async.wait_group 1;" ::: "memory")
#define CPW0()    asm volatile("cp.async.wait_group 0;" ::: "memory")

#define PIT 136
#define PITB 272
#define P64B 144

// ---------------------------------------------------------------------------
__global__ void prep_kernel(const float* __restrict__ Wq,
                            const float* __restrict__ Wk,
                            const float* __restrict__ Wv)
{
    const float* W = (blockIdx.x == 0) ? Wq : (blockIdx.x == 1) ? Wk : Wv;
    __nv_bfloat16* dh = g_Wth + blockIdx.x * DOUT * DIN;
    __nv_bfloat16* dl = g_Wtl + blockIdx.x * DOUT * DIN;
    for (int i = threadIdx.x; i < DOUT * (DIN/2); i += 256) {
        int n = i >> 7, k = (i & 127) * 2;
        float x0 = W[(size_t)k*DOUT + n];
        float x1 = W[(size_t)(k+1)*DOUT + n];
        *reinterpret_cast<uint32_t*>(dh + (size_t)n*DIN + k) = b2pack(x0, x1);
        *reinterpret_cast<uint32_t*>(dl + (size_t)n*DIN + k) =
            b2pack(x0 - bhi(x0), x1 - bhi(x1));
    }
}

// ---------------------------------------------------------------------------
// projmma: 256 threads, 8 warps (4m x 2n), warp tile 32x64 (mi=2).
// ---------------------------------------------------------------------------
__global__ __launch_bounds__(256, 1)
void projmma_kernel(const float* __restrict__ Y, const int* __restrict__ idx,
                    const float* __restrict__ bq, const float* __restrict__ bk,
                    const float* __restrict__ bv)
{
    extern __shared__ char smraw[];
    char* Ah = smraw;                    // 2 k-chunks x 34816
    char* Al = smraw + 69632;
    char* Bh = smraw + 139264;
    char* Bl = smraw + 174080;
    float* Vs = reinterpret_cast<float*>(Bh);
    __shared__ int idxs[128];

    const int tid = threadIdx.x, lane = tid & 31, wid = tid >> 5;
    const int wm = wid >> 1, wn = wid & 1;
    const int row0 = blockIdx.x * 128;
    const int b    = row0 / Mm;
    const int m0   = row0 % Mm;

    if (tid < 128) idxs[tid] = idx[b*Mm + m0 + tid];
    __syncthreads();

    for (int i = tid; i < 128*64; i += 256) {
        int row = i >> 6, c4 = i & 63;
        float4 y = *reinterpret_cast<const float4*>(
            Y + ((size_t)b*Nn + idxs[row])*DIN + c4*4);
        int kc = c4 >> 5;
        uint32_t off = (uint32_t)(kc*34816 + row*PITB + (c4 & 31)*8);
        *reinterpret_cast<uint2*>(Ah + off) =
            make_uint2(b2pack(y.x, y.y), b2pack(y.z, y.w));
        *reinterpret_cast<uint2*>(Al + off) =
            make_uint2(b2pack(y.x-bhi(y.x), y.y-bhi(y.y)),
                       b2pack(y.z-bhi(y.z), y.w-bhi(y.w)));
    }

    const uint32_t sAh = cvta_smem(Ah), sAl = cvta_smem(Al);
    const uint32_t sBh = cvta_smem(Bh), sBl = cvta_smem(Bl);

    const int aRow  = wm*32 + (lane & 15);
    const int aKb   = (lane >> 4) * 8;
    const int bRow4 = wn*64 + ((lane >> 4) << 3) + (lane & 7);
    const int bK4   = ((lane >> 3) & 1) * 8;

    #pragma unroll 1
    for (int wsel = 0; wsel < 3; wsel++) {
        float acc[2][8][4] = {};
        #pragma unroll 1
        for (int kc = 0; kc < 2; kc++) {
            __syncthreads();
            const __nv_bfloat16* wh = g_Wth + (size_t)wsel*DOUT*DIN + kc*128;
            const __nv_bfloat16* wl = g_Wtl + (size_t)wsel*DOUT*DIN + kc*128;
            for (int i = tid; i < 128*16; i += 256) {
                int n = i >> 4, c8 = i & 15;
                uint32_t off = (uint32_t)(n*PITB + c8*16);
                size_t go = (size_t)n*DIN + c8*8;
                *reinterpret_cast<uint4*>(Bh + off) =
                    *reinterpret_cast<const uint4*>(wh + go);
                *reinterpret_cast<uint4*>(Bl + off) =
                    *reinterpret_cast<const uint4*>(wl + go);
            }
            __syncthreads();
            uint32_t aBase = kc * 34816;
            #pragma unroll
            for (int term = 0; term < 3; term++) {
                uint32_t sA = ((term == 2) ? sAl : sAh) + aBase;
                uint32_t sB = (term == 1) ? sBl : sBh;
                #pragma unroll
                for (int ks = 0; ks < 8; ks++) {
                    uint32_t af[2][4];
                    #pragma unroll
                    for (int mi = 0; mi < 2; mi++)
                        ldmA(af[mi], sA + ((aRow + mi*16)*PIT + aKb + ks*16)*2);
                    #pragma unroll
                    for (int jj = 0; jj < 4; jj++) {
                        uint32_t bq4[4];
                        ldmB4(bq4, sB + ((bRow4 + jj*16)*PIT + bK4 + ks*16)*2);
                        #pragma unroll
                        for (int mi = 0; mi < 2; mi++) {
                            mma16816(acc[mi][2*jj],     af[mi], bq4);
                            mma16816(acc[mi][2*jj + 1], af[mi], bq4 + 2);
                        }
                    }
                }
            }
        }

        const float* bp = (wsel == 0) ? bq : (wsel == 1) ? bk : bv;
        float bias2[8][2];
        #pragma unroll
        for (int j = 0; j < 8; j++) {
            int c = wn*64 + j*8 + (lane & 3)*2;
            bias2[j][0] = bp[c]; bias2[j][1] = bp[c+1];
        }

        if (wsel < 2) {
            const float s = (wsel == 0) ? 0.0625f : 1.0f;
            __nv_bfloat16* gh = (wsel == 0) ? g_Qh : g_Kh;
            __nv_bfloat16* gl = (wsel == 0) ? g_Ql : g_Kl;
            #pragma unroll
            for (int mi = 0; mi < 2; mi++)
                #pragma unroll
                for (int j = 0; j < 8; j++) {
                    int r = wm*32 + mi*16 + (lane >> 2);
                    int c = wn*64 + j*8 + (lane & 3)*2;
                    float q0 = (acc[mi][j][0] + bias2[j][0]) * s;
                    float q1 = (acc[mi][j][1] + bias2[j][1]) * s;
                    float q2 = (acc[mi][j][2] + bias2[j][0]) * s;
                    float q3 = (acc[mi][j][3] + bias2[j][1]) * s;
                    size_t o0 = ((size_t)(b*Mm + m0 + r))*DOUT + c;
                    size_t o1 = ((size_t)(b*Mm + m0 + r + 8))*DOUT + c;
                    *reinterpret_cast<uint32_t*>(gh + o0) = b2pack(q0, q1);
                    *reinterpret_cast<uint32_t*>(gl + o0) =
                        b2pack(q0 - bhi(q0), q1 - bhi(q1));
                    *reinterpret_cast<uint32_t*>(gh + o1) = b2pack(q2, q3);
                    *reinterpret_cast<uint32_t*>(gl + o1) =
                        b2pack(q2 - bhi(q2), q3 - bhi(q3));
                }
        } else {
            __syncthreads();
            #pragma unroll
            for (int mi = 0; mi < 2; mi++)
                #pragma unroll
                for (int j = 0; j < 8; j++) {
                    int r = wm*32 + mi*16 + (lane >> 2);
                    int c = wn*64 + j*8 + (lane & 3)*2;
                    float v0 = fmaxf(acc[mi][j][0] + bias2[j][0], 0.f);
                    float v1 = fmaxf(acc[mi][j][1] + bias2[j][1], 0.f);
                    float v2 = fmaxf(acc[mi][j][2] + bias2[j][0], 0.f);
                    float v3 = fmaxf(acc[mi][j][3] + bias2[j][1], 0.f);
                    *reinterpret_cast<float2*>(
                        g_V + ((size_t)(b*Mm + m0 + r))*DOUT + c) = make_float2(v0, v1);
                    *reinterpret_cast<float2*>(
                        g_V + ((size_t)(b*Mm + m0 + r + 8))*DOUT + c) = make_float2(v2, v3);
                    Vs[r*132 + c]       = v0;
                    Vs[r*132 + c + 1]   = v1;
                    Vs[(r+8)*132 + c]   = v2;
                    Vs[(r+8)*132 + c+1] = v3;
                }
            __syncthreads();
            int e = tid & 127, half = tid >> 7;
            #pragma unroll
            for (int seg = 0; seg < 2; seg++) {
                int mb = half*64 + seg*32;
                uint32_t hp[16], lp[16];
                #pragma unroll
                for (int t = 0; t < 16; t++) {
                    float x0 = Vs[(mb + 2*t    )*132 + e];
                    float x1 = Vs[(mb + 2*t + 1)*132 + e];
                    hp[t] = b2pack(x0, x1);
                    lp[t] = b2pack(x0 - bhi(x0), x1 - bhi(x1));
                }
                uint4* dh = reinterpret_cast<uint4*>(
                    g_Vth + ((size_t)b*DOUT + e)*Mm + m0 + mb);
                uint4* dl = reinterpret_cast<uint4*>(
                    g_Vtl + ((size_t)b*DOUT + e)*Mm + m0 + mb);
                #pragma unroll
                for (int q = 0; q < 4; q++) {
                    dh[q] = make_uint4(hp[4*q],hp[4*q+1],hp[4*q+2],hp[4*q+3]);
                    dl[q] = make_uint4(lp[4*q],lp[4*q+1],lp[4*q+2],lp[4*q+3]);
                }
            }
        }
    }
}

// ---------------------------------------------------------------------------
// attnA: 256 threads, 8 warps (4m x 2n), warp tile 32x32, 3-stage ring.
// smem: Qh 34816 | Ql 34816 | 3 x Kbuf 34816 = 174080.
// ---------------------------------------------------------------------------
__global__ __launch_bounds__(256, 1)
void attnA_kernel(float* __restrict__ att)
{
    extern __shared__ char smraw[];
    const int tid = threadIdx.x, lane = tid & 31, wid = tid >> 5;
    const int b = blockIdx.y, m0 = blockIdx.x * 128;
    const int wm = wid >> 1, wn = wid & 1;

    char* Qh = smraw;
    char* Ql = smraw + 34816;
    char* Kb = smraw + 69632;
    const uint32_t sQh = cvta_smem(Qh), sQl = cvta_smem(Ql);
    const uint32_t sKb = cvta_smem(Kb);

    auto issueK = [&](int ch, int st) {
        const uint32_t dbase = sKb + st*34816;
        #pragma unroll
        for (int t = 0; t < 8; t++) {
            int i = tid + t*256;
            int tile = i >> 10, row = (i >> 4) & 63, p = i & 15;
            const __nv_bfloat16* src = (tile ? g_Kl : g_Kh)
                + ((size_t)(b*Mm + ch*64 + row))*DOUT + p*8;
            CPA(dbase + tile*17408 + row*PITB + p*16, src);
        }
        CPC();
    };

    issueK(0, 0);

    {
        const uint4* qh = reinterpret_cast<const uint4*>(g_Qh + ((size_t)b*Mm + m0)*DOUT);
        const uint4* ql = reinterpret_cast<const uint4*>(g_Ql + ((size_t)b*Mm + m0)*DOUT);
        for (int i = tid; i < 128*16; i += 256) {
            int row = i >> 4, c8 = i & 15;
            *reinterpret_cast<uint4*>(Qh + row*PITB + c8*16) = qh[i];
            *reinterpret_cast<uint4*>(Ql + row*PITB + c8*16) = ql[i];
        }
    }

    const int aRow  = wm*32 + (lane & 15);
    const int aKb   = (lane >> 4) * 8;
    const int bRow4 = wn*32 + ((lane >> 4) << 3) + (lane & 7);
    const int bK4   = ((lane >> 3) & 1) * 8;

    int st = 0;
    #pragma unroll 1
    for (int ch = 0; ch < 32; ch++) {
        int nst = (st == 2) ? 0 : st + 1;
        if (ch < 31) issueK(ch + 1, nst);
        if (ch < 31) { CPW1(); } else { CPW0(); }
        __syncthreads();

        const uint32_t kh = sKb + st*34816;
        const uint32_t kl = kh + 17408;

        float acc[2][4][4] = {};
        #pragma unroll
        for (int term = 0; term < 3; term++) {
            uint32_t sA = (term == 2) ? sQl : sQh;
            uint32_t sB = (term == 1) ? kl : kh;
            #pragma unroll
            for (int ks = 0; ks < 8; ks++) {
                uint32_t af[2][4];
                #pragma unroll
                for (int mi = 0; mi < 2; mi++)
                    ldmA(af[mi], sA + ((aRow + mi*16)*PIT + aKb + ks*16)*2);
                #pragma unroll
                for (int jj = 0; jj < 2; jj++) {
                    uint32_t bq4[4];
                    ldmB4(bq4, sB + (bRow4 + jj*16)*PITB + (bK4 + ks*16)*2);
                    #pragma unroll
                    for (int mi = 0; mi < 2; mi++) {
                        mma16816(acc[mi][2*jj],     af[mi], bq4);
                        mma16816(acc[mi][2*jj + 1], af[mi], bq4 + 2);
                    }
                }
            }
        }

        #pragma unroll
        for (int mi = 0; mi < 2; mi++)
            #pragma unroll
            for (int j = 0; j < 4; j++) {
                int r = wm*32 + mi*16 + (lane >> 2);
                int c = ch*64 + wn*32 + j*8 + (lane & 3)*2;
                *reinterpret_cast<float2*>(
                    att + ((size_t)(b*Mm + m0 + r))*Mm + c) =
                    make_float2(acc[mi][j][0], acc[mi][j][1]);
                *reinterpret_cast<float2*>(
                    att + ((size_t)(b*Mm + m0 + r + 8))*Mm + c) =
                    make_float2(acc[mi][j][2], acc[mi][j][3]);
            }
        st = nst;
    }
    __syncthreads();

    // softmax: warp wid owns rows [wid*16, wid*16+16); emits fp32 + bf16 split
    #pragma unroll 1
    for (int rr = 0; rr < 16; rr++) {
        size_t rowi = (size_t)(b*Mm + m0 + wid*16 + rr);
        float* row = att + rowi*Mm;
        float4 v[16];
        #pragma unroll
        for (int j = 0; j < 16; j++) v[j] = reinterpret_cast<float4*>(row)[lane + j*32];
        float mx = -1e30f;
        #pragma unroll
        for (int j = 0; j < 16; j++)
            mx = fmaxf(mx, fmaxf(fmaxf(v[j].x, v[j].y), fmaxf(v[j].z, v[j].w)));
        #pragma unroll
        for (int o = 16; o > 0; o >>= 1) mx = fmaxf(mx, __shfl_xor_sync(0xffffffffu, mx, o));
        float sum = 0.f;
        #pragma unroll
        for (int j = 0; j < 16; j++) {
            v[j].x = __expf(v[j].x - mx); v[j].y = __expf(v[j].y - mx);
            v[j].z = __expf(v[j].z - mx); v[j].w = __expf(v[j].w - mx);
            sum += (v[j].x + v[j].y) + (v[j].z + v[j].w);
        }
        #pragma unroll
        for (int o = 16; o > 0; o >>= 1) sum += __shfl_xor_sync(0xffffffffu, sum, o);
        float inv = 1.f / sum;
        uint2* ah = reinterpret_cast<uint2*>(g_Ah + rowi*Mm);
        uint2* al = reinterpret_cast<uint2*>(g_Al + rowi*Mm);
        #pragma unroll
        for (int j = 0; j < 16; j++) {
            v[j].x *= inv; v[j].y *= inv; v[j].z *= inv; v[j].w *= inv;
            reinterpret_cast<float4*>(row)[lane + j*32] = v[j];
            ah[lane + j*32] = make_uint2(b2pack(v[j].x, v[j].y), b2pack(v[j].z, v[j].w));
            al[lane + j*32] = make_uint2(
                b2pack(v[j].x - bhi(v[j].x), v[j].y - bhi(v[j].y)),
                b2pack(v[j].z - bhi(v[j].z), v[j].w - bhi(v[j].w)));
        }
    }
}

// ---------------------------------------------------------------------------
// attnC: 256 threads, 8 warps (4m x 2n), warp tile 32x64, 3-stage ring.
// smem: 3 x (Ah|Al|Bh|Bl each 18432) = 221184.
// ---------------------------------------------------------------------------
__global__ __launch_bounds__(256, 1)
void attnC_kernel(float* __restrict__ out)
{
    extern __shared__ char smraw[];
    const int tid = threadIdx.x, lane = tid & 31, wid = tid >> 5;
    const int b = blockIdx.y, m0 = blockIdx.x * 128;
    const int wm = wid >> 1, wn = wid & 1;

    const uint32_t sb = cvta_smem(smraw);

    auto issueC = [&](int ch, int st) {
        const uint32_t dbase = sb + st*73728;
        #pragma unroll
        for (int t = 0; t < 16; t++) {
            int i = tid + t*256;
            int tile = i >> 10, row = (i >> 3) & 127, p = i & 7;
            const __nv_bfloat16* src;
            if (tile == 0)
                src = g_Ah + ((size_t)(b*Mm + m0 + row))*Mm + ch*64 + p*8;
            else if (tile == 1)
                src = g_Al + ((size_t)(b*Mm + m0 + row))*Mm + ch*64 + p*8;
            else if (tile == 2)
                src = g_Vth + ((size_t)(b*DOUT + row))*Mm + ch*64 + p*8;
            else
                src = g_Vtl + ((size_t)(b*DOUT + row))*Mm + ch*64 + p*8;
            CPA(dbase + tile*18432 + row*P64B + p*16, src);
        }
        CPC();
    };

    issueC(0, 0);

    const int aRow  = wm*32 + (lane & 15);
    const int aKb   = (lane >> 4) * 8;
    const int bRow4 = wn*64 + ((lane >> 4) << 3) + (lane & 7);
    const int bK4   = ((lane >> 3) & 1) * 8;

    float acc[2][8][4] = {};

    int st = 0;
    #pragma unroll 1
    for (int ch = 0; ch < 32; ch++) {
        int nst = (st == 2) ? 0 : st + 1;
        if (ch < 31) issueC(ch + 1, nst);
        if (ch < 31) { CPW1(); } else { CPW0(); }
        __syncthreads();

        const uint32_t base = sb + st*73728;
        const uint32_t tAh = base, tAl = base + 18432;
        const uint32_t tBh = base + 36864, tBl = base + 55296;

        #pragma unroll
        for (int term = 0; term < 3; term++) {
            uint32_t sA = (term == 2) ? tAl : tAh;
            uint32_t sB = (term == 1) ? tBl : tBh;
            #pragma unroll
            for (int ks = 0; ks < 4; ks++) {
                uint32_t af[2][4];
                #pragma unroll
                for (int mi = 0; mi < 2; mi++)
                    ldmA(af[mi], sA + (aRow + mi*16)*P64B + (aKb + ks*16)*2);
                #pragma unroll
                for (int jj = 0; jj < 4; jj++) {
                    uint32_t bq4[4];
                    ldmB4(bq4, sB + (bRow4 + jj*16)*P64B + (bK4 + ks*16)*2);
                    #pragma unroll
                    for (int mi = 0; mi < 2; mi++) {
                        mma16816(acc[mi][2*jj],     af[mi], bq4);
                        mma16816(acc[mi][2*jj + 1], af[mi], bq4 + 2);
                    }
                }
            }
        }
        st = nst;
    }
    __syncthreads();   // all MMA done before Ss overwrites stage 0

    float* Ss = reinterpret_cast<float*>(smraw);
    #pragma unroll
    for (int mi = 0; mi < 2; mi++)
        #pragma unroll
        for (int j = 0; j < 8; j++) {
            int r = wm*32 + mi*16 + (lane >> 2);
            int c = wn*64 + j*8 + (lane & 3)*2;
            Ss[r*132 + c]         = acc[mi][j][0];
            Ss[r*132 + c + 1]     = acc[mi][j][1];
            Ss[(r+8)*132 + c]     = acc[mi][j][2];
            Ss[(r+8)*132 + c + 1] = acc[mi][j][3];
        }
    __syncthreads();

    #pragma unroll 1
    for (int rr = 0; rr < 16; rr++) {
        int r = wid*16 + rr;
        float a0 = Ss[r*132 + lane],      a1 = Ss[r*132 + lane + 32];
        float a2 = Ss[r*132 + lane + 64], a3 = Ss[r*132 + lane + 96];
        float ss = a0*a0 + a1*a1 + a2*a2 + a3*a3;
        #pragma unroll
        for (int o = 16; o > 0; o >>= 1) ss += __shfl_xor_sync(0xffffffffu, ss, o);
        float inv1 = rsqrtf(fmaxf(ss, 1e-12f));
        const float* vrow = g_V + ((size_t)b*Mm + m0 + r)*DOUT;
        float t0 = vrow[lane]      + a0*inv1;
        float t1 = vrow[lane + 32] + a1*inv1;
        float t2 = vrow[lane + 64] + a2*inv1;
        float t3 = vrow[lane + 96] + a3*inv1;
        float ss2 = t0*t0 + t1*t1 + t2*t2 + t3*t3;
        #pragma unroll
        for (int o = 16; o > 0; o >>= 1) ss2 += __shfl_xor_sync(0xffffffffu, ss2, o);
        float inv2 = rsqrtf(fmaxf(ss2, 1e-12f));
        float* orow = out + ((size_t)b*Mm + m0 + r)*DOUT;
        orow[lane]      = t0*inv2;
        orow[lane + 32] = t1*inv2;
        orow[lane + 64] = t2*inv2;
        orow[lane + 96] = t3*inv2;
    }
}

// ---------------------------------------------------------------------------
extern "C" void kernel_launch(void* const* d_in, const int* in_sizes, int n_in,
                              void* d_out, int out_size)
{
    const float* Y   = (const float*)d_in[0];
    const int*   idx = (const int*)  d_in[1];
    const float* Wq  = (const float*)d_in[2];
    const float* bq  = (const float*)d_in[3];
    const float* Wk  = (const float*)d_in[4];
    const float* bk  = (const float*)d_in[5];
    const float* Wv  = (const float*)d_in[6];
    const float* bv  = (const float*)d_in[7];

    float* out = (float*)d_out;                       // [8,2048,128]
    float* att = out + (size_t)Bb*Mm*DOUT;            // [8,2048,2048]

    const int smemP = 208896;
    const int smemA = 174080;
    const int smemC = 221184;

    cudaFuncSetAttribute(projmma_kernel, cudaFuncAttributeMaxDynamicSharedMemorySize, smemP);
    cudaFuncSetAttribute(attnA_kernel,   cudaFuncAttributeMaxDynamicSharedMemorySize, smemA);
    cudaFuncSetAttribute(attnC_kernel,   cudaFuncAttributeMaxDynamicSharedMemorySize, smemC);

    prep_kernel<<<3, 256>>>(Wq, Wk, Wv);
    projmma_kernel<<<(Bb*Mm)/128, 256, smemP>>>(Y, idx, bq, bk, bv);
    attnA_kernel<<<dim3(Mm/128, Bb), 256, smemA>>>(att);
    attnC_kernel<<<dim3(Mm/128, Bb), 256, smemC>>>(out);
}